// round 2
// baseline (speedup 1.0000x reference)
#include <cuda_runtime.h>
#include <math.h>

#define EMB    1024
#define NDEC   2048     // WIDTH*MODES*2
#define WIDTH  64
#define MODES  16
#define NH     128      // fc1 hidden
#define MAXB   64
#define KC     16       // K-split chunks in stage A
#define KCHUNK 64       // EMB / KC
#define OT     256      // output-column tile in stage A
#define NKK    31       // 1 DC + 15 cos + 15 sin
#define TT     64       // t-tile in stage C

// Scratch (static device globals; no allocation)
__device__ float g_hpart[KC][MAXB * NDEC];   // 8 MB
__device__ float g_coef[MAXB * NKK * NH];    // ~1 MB

// ---------------------------------------------------------------------------
// Stage A: partial GEMM  h_part[c][b][o] = sum_{e in chunk c} token[b][e]*wdec[e][o]
// grid: (NDEC/OT, KC), block: OT threads. Each thread owns one output column o
// and accumulates all 64 batch rows in registers.
// ---------------------------------------------------------------------------
__global__ void stageA(const float* __restrict__ token,
                       const float* __restrict__ wdec, int B) {
    __shared__ float tok[MAXB][KCHUNK];
    const int o  = blockIdx.x * OT + threadIdx.x;
    const int k0 = blockIdx.y * KCHUNK;

    for (int i = threadIdx.x; i < MAXB * KCHUNK; i += OT) {
        int b = i >> 6, e = i & 63;
        tok[b][e] = (b < B) ? token[b * EMB + k0 + e] : 0.0f;
    }
    __syncthreads();

    float acc[MAXB];
#pragma unroll
    for (int b = 0; b < MAXB; b++) acc[b] = 0.0f;

#pragma unroll 4
    for (int e = 0; e < KCHUNK; e++) {
        float wv = wdec[(size_t)(k0 + e) * NDEC + o];
#pragma unroll
        for (int b = 0; b < MAXB; b++) acc[b] += tok[b][e] * wv;
    }

    float* dst = g_hpart[blockIdx.y];
#pragma unroll
    for (int b = 0; b < MAXB; b++) dst[b * NDEC + o] = acc[b];
}

// ---------------------------------------------------------------------------
// Stage B: reduce K-split partials + bias, then fold irfft scales + fc1 weight
// into per-batch trig coefficients:
//   Coef[b][0][j]    = (1/L)  * sum_w re[b,w,0] * w1[w,j]        (DC; Im ignored)
//   Coef[b][k][j]    = (2/L)  * sum_w re[b,w,k] * w1[w,j]  k=1..15   (cos)
//   Coef[b][15+k][j] = (-2/L) * sum_w im[b,w,k] * w1[w,j]  k=1..15   (sin)
// h layout per row: idx = w*32 + k*2 + {0=re,1=im}
// ---------------------------------------------------------------------------
__global__ void stageB(const float* __restrict__ w1,
                       const float* __restrict__ bdec, float invL) {
    __shared__ float hs[NDEC];
    __shared__ float w1s[WIDTH * NH];
    const int b = blockIdx.x;
    const int j = threadIdx.x;  // 128 threads

    for (int i = j; i < NDEC; i += NH) {
        float s = bdec[i];
#pragma unroll
        for (int c = 0; c < KC; c++) s += g_hpart[c][b * NDEC + i];
        hs[i] = s;
    }
    for (int i = j; i < WIDTH * NH; i += NH)  w1s[i] = w1[i];
    __syncthreads();

    {   // DC term
        float a = 0.0f;
#pragma unroll
        for (int w = 0; w < WIDTH; w++) a += hs[w * 32] * w1s[w * NH + j];
        g_coef[(b * NKK + 0) * NH + j] = a * invL;
    }
#pragma unroll
    for (int k = 1; k < MODES; k++) {
        float ac = 0.0f, as = 0.0f;
#pragma unroll
        for (int w = 0; w < WIDTH; w++) {
            float wv = w1s[w * NH + j];
            ac += hs[w * 32 + k * 2]     * wv;
            as += hs[w * 32 + k * 2 + 1] * wv;
        }
        g_coef[(b * NKK + k)      * NH + j] = ac * (2.0f * invL);
        g_coef[(b * NKK + 15 + k) * NH + j] = as * (-2.0f * invL);
    }
}

// ---------------------------------------------------------------------------
// Stage C: main loop. grid (ceil(TL/TT), B), 128 threads (j-dim).
// Per t: pre = C0 + b1 + sum_k (Ck*cos + Sk*sin); gelu(exact); dot with w2.
// ---------------------------------------------------------------------------
__global__ void __launch_bounds__(NH) stageC(
        const float* __restrict__ b1, const float* __restrict__ w2,
        const float* __restrict__ b2, float* __restrict__ out,
        float omega, int TL) {
    __shared__ float2 trig[TT][MODES];   // [t][m] = {cos((m+1)wt), sin((m+1)wt)}
    __shared__ float  wsum[TT][4];

    const int b  = blockIdx.y;
    const int t0 = blockIdx.x * TT;
    const int j  = threadIdx.x;

    // cooperative trig table fill: 16 slots per t, slot 15 unused
    for (int i = j; i < TT * MODES; i += NH) {
        int t = i >> 4;
        int m = i & 15;
        if (m < MODES - 1) {
            float ang = omega * (float)((m + 1) * (t0 + t));
            float s, c;
            sincosf(ang, &s, &c);
            trig[t][m] = make_float2(c, s);
        }
    }

    // per-thread coefficients in registers
    const float* cf = g_coef + (size_t)b * NKK * NH + j;
    float c0 = cf[0];
    float cc[MODES - 1], sv[MODES - 1];
#pragma unroll
    for (int m = 0; m < MODES - 1; m++) {
        cc[m] = cf[(1 + m)  * NH];
        sv[m] = cf[(16 + m) * NH];
    }
    const float b1j = b1[j];
    const float w2j = w2[j];
    __syncthreads();

    const int warp = j >> 5, lane = j & 31;

    for (int tt = 0; tt < TT; tt++) {
        float p0 = c0 + b1j;
        float p1 = 0.0f;
#pragma unroll
        for (int m = 0; m < MODES - 1; m++) {
            float2 v = trig[tt][m];
            p0 += cc[m] * v.x;
            p1 += sv[m] * v.y;
        }
        float p = p0 + p1;
        // exact gelu: 0.5*x*(1+erf(x/sqrt(2)))
        float g = 0.5f * p * (1.0f + erff(p * 0.70710678118654752440f));
        float v = g * w2j;
#pragma unroll
        for (int off = 16; off; off >>= 1)
            v += __shfl_down_sync(0xffffffffu, v, off);
        if (lane == 0) wsum[tt][warp] = v;
    }
    __syncthreads();

    const float b2v = b2[0];
    for (int tt = j; tt < TT; tt += NH) {
        int t = t0 + tt;
        if (t < TL)
            out[(size_t)b * TL + t] =
                wsum[tt][0] + wsum[tt][1] + wsum[tt][2] + wsum[tt][3] + b2v;
    }
}

// ---------------------------------------------------------------------------
extern "C" void kernel_launch(void* const* d_in, const int* in_sizes, int n_in,
                              void* d_out, int out_size) {
    // inputs: token, [x_len], w_dec, b_dec, w1, b1, w2, b2
    const int off = (n_in == 8) ? 1 : 0;
    const float* token = (const float*)d_in[0];
    const float* wdec  = (const float*)d_in[1 + off];
    const float* bdec  = (const float*)d_in[2 + off];
    const float* w1    = (const float*)d_in[3 + off];
    const float* b1    = (const float*)d_in[4 + off];
    const float* w2    = (const float*)d_in[5 + off];
    const float* b2    = (const float*)d_in[6 + off];
    float* out = (float*)d_out;

    int B  = in_sizes[0] / EMB;         // 64
    int TL = out_size / B;              // L - 2 = 8190
    int L  = TL + 2;                    // 8192
    float invL  = 1.0f / (float)L;
    float omega = (float)(2.0 * 3.14159265358979323846 / (double)L);

    stageA<<<dim3(NDEC / OT, KC), OT>>>(token, wdec, B);

    stageB<<<B, NH>>>(w1, bdec, invL);

    stageC<<<dim3((TL + TT - 1) / TT, B), NH>>>(b1, w2, b2, out, omega, TL);
}

// round 4
// speedup vs baseline: 1.1448x; 1.1448x over previous
#include <cuda_runtime.h>
#include <math.h>

#define EMB    1024
#define NDEC   2048     // WIDTH*MODES*2
#define WIDTH  64
#define MODES  16
#define NH     128      // fc1 hidden
#define MAXB   64
#define KC     32       // K-split chunks in stage A
#define KCHUNK 32       // EMB / KC
#define OT     256      // output-column tile in stage A
#define NKK    31       // 1 DC + 15 cos + 15 sin
#define TT     64       // t-tile per block in stage C
#define TW     16       // t per warp in stage C
#define NM     15       // MODES-1

// Scratch (static device globals; no allocation)
__device__ float g_hpart[KC][MAXB * NDEC];   // 16 MB
__device__ float g_coef[MAXB * NKK * NH];    // ~1 MB

// ---- packed f32x2 helpers (sm_100+) --------------------------------------
__device__ __forceinline__ unsigned long long pk2(float lo, float hi) {
    unsigned long long r;
    asm("mov.b64 %0, {%1, %2};" : "=l"(r) : "f"(lo), "f"(hi));
    return r;
}
__device__ __forceinline__ void upk2(unsigned long long v, float& lo, float& hi) {
    asm("mov.b64 {%0, %1}, %2;" : "=f"(lo), "=f"(hi) : "l"(v));
}
__device__ __forceinline__ unsigned long long ffma2(
        unsigned long long a, unsigned long long b, unsigned long long c) {
    unsigned long long d;
    asm("fma.rn.f32x2 %0, %1, %2, %3;" : "=l"(d) : "l"(a), "l"(b), "l"(c));
    return d;
}
__device__ __forceinline__ unsigned long long fadd2(
        unsigned long long a, unsigned long long b) {
    unsigned long long d;
    asm("add.rn.f32x2 %0, %1, %2;" : "=l"(d) : "l"(a), "l"(b));
    return d;
}

// exact-enough gelu: Taylor erf for small args (the real case), erff fallback
__device__ __forceinline__ float gelu_f(float x) {
    float u  = x * 0.70710678118654752440f;
    float u2 = u * u;
    float e;
    if (u2 < 0.49f) {
        // erf(u) = (2/sqrt(pi)) * u * (1 - u2/3 + u2^2/10 - u2^3/42 + u2^4/216)
        float t = fmaf(u2, 1.0f / 216.0f, -1.0f / 42.0f);
        t = fmaf(t, u2, 0.1f);
        t = fmaf(t, u2, -1.0f / 3.0f);
        t = fmaf(t, u2, 1.0f);
        e = (1.12837916709551257390f * u) * t;
    } else {
        e = erff(u);
    }
    return x * fmaf(0.5f, e, 0.5f);
}

// ---------------------------------------------------------------------------
// Stage A: partial GEMM  h_part[c][b][o] = sum_{e in chunk c} token[b][e]*wdec[e][o]
// grid: (NDEC/OT, KC) = (8, 32) = 256 blocks, OT threads; each thread owns one
// output column o and accumulates all 64 batch rows in registers.
// ---------------------------------------------------------------------------
__global__ void __launch_bounds__(OT) stageA(const float* __restrict__ token,
                                             const float* __restrict__ wdec, int B) {
    __shared__ float tok[MAXB][KCHUNK];
    const int o  = blockIdx.x * OT + threadIdx.x;
    const int k0 = blockIdx.y * KCHUNK;

    for (int i = threadIdx.x; i < MAXB * KCHUNK; i += OT) {
        int bb = i / KCHUNK, e = i % KCHUNK;
        tok[bb][e] = (bb < B) ? token[bb * EMB + k0 + e] : 0.0f;
    }
    __syncthreads();

    float acc[MAXB];
#pragma unroll
    for (int bb = 0; bb < MAXB; bb++) acc[bb] = 0.0f;

    const float* wp = wdec + (size_t)k0 * NDEC + o;
#pragma unroll 8
    for (int e = 0; e < KCHUNK; e++) {
        float wv = wp[(size_t)e * NDEC];
#pragma unroll
        for (int bb = 0; bb < MAXB; bb++) acc[bb] += tok[bb][e] * wv;
    }

    float* dst = g_hpart[blockIdx.y];
#pragma unroll
    for (int bb = 0; bb < MAXB; bb++) dst[bb * NDEC + o] = acc[bb];
}

// ---------------------------------------------------------------------------
// Stage B: reduce K-split partials + bias, then fold irfft scales + fc1 weight
// into per-batch trig coefficients:
//   Coef[b][0][j]    = (1/L)  * sum_w re[b,w,0] * w1[w,j]        (DC; Im ignored)
//   Coef[b][k][j]    = (2/L)  * sum_w re[b,w,k] * w1[w,j]  k=1..15   (cos)
//   Coef[b][15+k][j] = (-2/L) * sum_w im[b,w,k] * w1[w,j]  k=1..15   (sin)
// h layout per row: idx = w*32 + k*2 + {0=re,1=im}
// ---------------------------------------------------------------------------
__global__ void stageB(const float* __restrict__ w1,
                       const float* __restrict__ bdec, float invL) {
    __shared__ float hs[NDEC];
    __shared__ float w1s[WIDTH * NH];
    const int b = blockIdx.x;
    const int j = threadIdx.x;  // 128 threads

    for (int i = j; i < NDEC; i += NH) {
        float s = bdec[i];
#pragma unroll
        for (int c = 0; c < KC; c++) s += g_hpart[c][b * NDEC + i];
        hs[i] = s;
    }
    for (int i = j; i < WIDTH * NH; i += NH) w1s[i] = w1[i];
    __syncthreads();

    {   // DC term
        float a = 0.0f;
#pragma unroll
        for (int w = 0; w < WIDTH; w++) a += hs[w * 32] * w1s[w * NH + j];
        g_coef[(b * NKK + 0) * NH + j] = a * invL;
    }
#pragma unroll
    for (int k = 1; k < MODES; k++) {
        float ac = 0.0f, as = 0.0f;
#pragma unroll
        for (int w = 0; w < WIDTH; w++) {
            float wv = w1s[w * NH + j];
            ac += hs[w * 32 + k * 2]     * wv;
            as += hs[w * 32 + k * 2 + 1] * wv;
        }
        g_coef[(b * NKK + k)      * NH + j] = ac * (2.0f * invL);
        g_coef[(b * NKK + 15 + k) * NH + j] = as * (-2.0f * invL);
    }
}

// ---------------------------------------------------------------------------
// Stage C: grid ((TL+TT-1)/TT, B), 128 threads. Each WARP owns TW=16 t values
// and all 128 j (4 j per thread, packed f32x2). Warp-private trig table holds
// pre-duplicated (c,c),(s,s) pairs so one LDS.128 feeds 4 FFMA2.
// No __syncthreads anywhere.
// ---------------------------------------------------------------------------
__global__ void __launch_bounds__(NH) stageC(
        const float* __restrict__ b1, const float* __restrict__ w2,
        const float* __restrict__ b2, float* __restrict__ out,
        float omega, int TL, int L, int lmask) {
    __shared__ ulonglong2 tab[4 * TW * NM];   // [warp][tl][m] = {(c,c),(s,s)}

    const int b    = blockIdx.y;
    const int j    = threadIdx.x;
    const int warp = j >> 5, lane = j & 31;
    const int tw0  = blockIdx.x * TT + warp * TW;   // this warp's first t

    // fill warp-private trig table (exact integer angle reduction + __sincosf)
    ulonglong2* mytab = tab + warp * TW * NM;
    for (int i = lane; i < TW * NM; i += 32) {
        int tl = i / NM, m = i - tl * NM;
        int v  = (m + 1) * (tw0 + tl);
        int r  = (lmask >= 0) ? (v & lmask) : (v % L);
        float ang = omega * (float)r;
        float s, c;
        __sincosf(ang, &s, &c);
        mytab[i] = make_ulonglong2(pk2(c, c), pk2(s, s));
    }

    // per-thread coefficients: j0..j3 = lane, lane+32, lane+64, lane+96
    const float* cf = g_coef + (size_t)b * NKK * NH;
    const int j0 = lane, j1 = lane + 32, j2 = lane + 64, j3 = lane + 96;
    const unsigned long long c01 = pk2(cf[j0] + b1[j0], cf[j1] + b1[j1]);
    const unsigned long long c23 = pk2(cf[j2] + b1[j2], cf[j3] + b1[j3]);
    unsigned long long cc01[NM], cc23[NM], sv01[NM], sv23[NM];
#pragma unroll
    for (int m = 0; m < NM; m++) {
        const float* p = cf + (1 + m) * NH;
        cc01[m] = pk2(p[j0], p[j1]);
        cc23[m] = pk2(p[j2], p[j3]);
        const float* q = cf + (16 + m) * NH;
        sv01[m] = pk2(q[j0], q[j1]);
        sv23[m] = pk2(q[j2], q[j3]);
    }
    const float w20 = w2[j0], w21 = w2[j1], w22 = w2[j2], w23 = w2[j3];
    const float b2v = b2[0];
    __syncwarp();

#pragma unroll 2
    for (int tl = 0; tl < TW; tl++) {
        unsigned long long a01 = c01, a23 = c23, s01 = 0ULL, s23 = 0ULL;
        const ulonglong2* tp = mytab + tl * NM;
#pragma unroll
        for (int m = 0; m < NM; m++) {
            ulonglong2 q = tp[m];
            a01 = ffma2(cc01[m], q.x, a01);
            a23 = ffma2(cc23[m], q.x, a23);
            s01 = ffma2(sv01[m], q.y, s01);
            s23 = ffma2(sv23[m], q.y, s23);
        }
        unsigned long long p01 = fadd2(a01, s01), p23 = fadd2(a23, s23);
        float p0, p1, p2, p3;
        upk2(p01, p0, p1);
        upk2(p23, p2, p3);
        float v = gelu_f(p0) * w20;
        v = fmaf(gelu_f(p1), w21, v);
        v = fmaf(gelu_f(p2), w22, v);
        v = fmaf(gelu_f(p3), w23, v);
#pragma unroll
        for (int off = 16; off; off >>= 1)
            v += __shfl_xor_sync(0xffffffffu, v, off);
        int t = tw0 + tl;
        if (lane == 0 && t < TL)
            out[(size_t)b * TL + t] = v + b2v;
    }
}

// ---------------------------------------------------------------------------
extern "C" void kernel_launch(void* const* d_in, const int* in_sizes, int n_in,
                              void* d_out, int out_size) {
    // inputs: token, [x_len], w_dec, b_dec, w1, b1, w2, b2
    const int off = (n_in == 8) ? 1 : 0;
    const float* token = (const float*)d_in[0];
    const float* wdec  = (const float*)d_in[1 + off];
    const float* bdec  = (const float*)d_in[2 + off];
    const float* w1    = (const float*)d_in[3 + off];
    const float* b1    = (const float*)d_in[4 + off];
    const float* w2    = (const float*)d_in[5 + off];
    const float* b2    = (const float*)d_in[6 + off];
    float* out = (float*)d_out;

    int B  = in_sizes[0] / EMB;         // 64
    int TL = out_size / B;              // L - 2 = 8190
    int L  = TL + 2;                    // 8192
    float invL  = 1.0f / (float)L;
    float omega = (float)(2.0 * 3.14159265358979323846 / (double)L);
    int lmask = ((L & (L - 1)) == 0) ? (L - 1) : -1;

    stageA<<<dim3(NDEC / OT, KC), OT>>>(token, wdec, B);

    stageB<<<B, NH>>>(w1, bdec, invL);

    stageC<<<dim3((TL + TT - 1) / TT, B), NH>>>(b1, w2, b2, out, omega, TL, L, lmask);
}